// round 5
// baseline (speedup 1.0000x reference)
#include <cuda_runtime.h>
#include <cuda_fp16.h>
#include <math.h>
#include <stdint.h>

#define MROWS 2048
#define EMB   512

// ---------------- scratch (device globals) -----------------------------------
__device__ float  g_T1 [4UL*2048*512];
__device__ float  g_R1 [4UL*2048*512];
__device__ float  g_T2 [4UL*2048*512];
__device__ __half g_Xh [4UL*2048*512];
__device__ __half g_Q  [4UL*2048*512];   // [s,b,h,t,d]
__device__ __half g_K  [4UL*2048*512];
__device__ __half g_V  [4UL*2048*512];
__device__ __half g_MH [4UL*2048*512];   // pre-transposed attention out
__device__ __half g_R1h[4UL*2048*512];
__device__ __half g_HB [4UL*2048*2048];
__device__ __half g_Wqh[4UL*512*512];
__device__ __half g_Wkh[4UL*512*512];
__device__ __half g_Wvh[4UL*512*512];
__device__ __half g_Woh[4UL*512*512];
__device__ __half g_W1h[4UL*512*2048];
__device__ __half g_W2h[4UL*2048*512];

struct R4 { const float* p[4]; };

__device__ __forceinline__ float gelu_exact(float x) {
    return 0.5f * x * (1.0f + erff(x * 0.70710678118654752440f));
}
__device__ __forceinline__ uint32_t sptr(const void* p) {
    return (uint32_t)__cvta_generic_to_shared(p);
}
__device__ __forceinline__ void cpa16(void* s, const void* g) {
    asm volatile("cp.async.cg.shared.global [%0],[%1],16;\n" :: "r"(sptr(s)), "l"(g));
}
__device__ __forceinline__ void ldsm4(uint32_t& r0, uint32_t& r1, uint32_t& r2,
                                      uint32_t& r3, uint32_t a) {
    asm volatile("ldmatrix.sync.aligned.m8n8.x4.shared.b16 {%0,%1,%2,%3},[%4];\n"
        : "=r"(r0), "=r"(r1), "=r"(r2), "=r"(r3) : "r"(a));
}
__device__ __forceinline__ void ldsm4t(uint32_t& r0, uint32_t& r1, uint32_t& r2,
                                       uint32_t& r3, uint32_t a) {
    asm volatile("ldmatrix.sync.aligned.m8n8.x4.trans.shared.b16 {%0,%1,%2,%3},[%4];\n"
        : "=r"(r0), "=r"(r1), "=r"(r2), "=r"(r3) : "r"(a));
}
__device__ __forceinline__ void mmaf16(float& d0, float& d1, float& d2, float& d3,
    uint32_t a0, uint32_t a1, uint32_t a2, uint32_t a3, uint32_t b0, uint32_t b1) {
    asm volatile("mma.sync.aligned.m16n8k16.row.col.f32.f16.f16.f32 "
        "{%0,%1,%2,%3},{%4,%5,%6,%7},{%8,%9},{%0,%1,%2,%3};\n"
        : "+f"(d0), "+f"(d1), "+f"(d2), "+f"(d3)
        : "r"(a0), "r"(a1), "r"(a2), "r"(a3), "r"(b0), "r"(b1));
}
__device__ __forceinline__ uint32_t packh2(float x, float y) {
    __half2 h = __floats2half2_rn(x, y);
    return *(uint32_t*)&h;
}

// ---------------- batched fp32->fp16 converters --------------------------------
// 4 small weight sets (each 4*512*512 elems), selected by blockIdx.y
__global__ __launch_bounds__(256)
void cvt4_kernel(const float* w0, const float* w1, const float* w2, const float* w3)
{
    int wsel = blockIdx.y;
    const float* s = wsel == 0 ? w0 : wsel == 1 ? w1 : wsel == 2 ? w2 : w3;
    __half* d = wsel == 0 ? g_Wqh : wsel == 1 ? g_Wkh : wsel == 2 ? g_Wvh : g_Woh;
    int i = (blockIdx.x * 256 + threadIdx.x) * 4;
    float4 v = *(const float4*)(s + i);
    *(__half2*)(d + i)     = __floats2half2_rn(v.x, v.y);
    *(__half2*)(d + i + 2) = __floats2half2_rn(v.z, v.w);
}
// big: W1, W2 (each 4*512*2048) by blockIdx.y
__global__ __launch_bounds__(256)
void cvt2_kernel(const float* w1, const float* w2)
{
    const float* s = blockIdx.y == 0 ? w1 : w2;
    __half* d = blockIdx.y == 0 ? g_W1h : g_W2h;
    int i = (blockIdx.x * 256 + threadIdx.x) * 4;
    float4 v = *(const float4*)(s + i);
    *(__half2*)(d + i)     = __floats2half2_rn(v.x, v.y);
    *(__half2*)(d + i + 2) = __floats2half2_rn(v.z, v.w);
}
__global__ __launch_bounds__(256)
void xcvt_kernel(const float* __restrict__ x0, const float* __restrict__ x1,
                 const float* __restrict__ x2, const float* __restrict__ x3) {
    int s = blockIdx.y;
    const float* x = s == 0 ? x0 : s == 1 ? x1 : s == 2 ? x2 : x3;
    int i = (blockIdx.x * 256 + threadIdx.x) * 4;
    float4 v = *(const float4*)(x + i);
    __half* d = g_Xh + (size_t)s * MROWS * EMB + i;
    *(__half2*)(d)     = __floats2half2_rn(v.x, v.y);
    *(__half2*)(d + 2) = __floats2half2_rn(v.z, v.w);
}

// ---------------- fp16 MMA GEMM core: 128x128x32, 256 thr ---------------------
#define LDA 40
#define LDB 152
#define AS_SZ (128*LDA)
#define BS_SZ (32*LDB)

__device__ __forceinline__ void stage_h(const __half* Ag, const __half* Bg,
    int K, int N, __half* Ad, __half* Bd, int tid)
{
    #pragma unroll
    for (int i = 0; i < 2; ++i) {
        int c = tid + (i << 8);
        int ar = c >> 2, ac = (c & 3) << 3;
        cpa16(Ad + ar * LDA + ac, Ag + (size_t)ar * K + ac);
        int br = c >> 4, bn = (c & 15) << 3;
        cpa16(Bd + br * LDB + bn, Bg + (size_t)br * N + bn);
    }
    asm volatile("cp.async.commit_group;\n" ::: "memory");
}

__device__ __forceinline__ void mainloop_h(
    const __half* __restrict__ A, const __half* __restrict__ B,
    int K, int N, int m0, int n0, float (&acc)[4][4][4],
    __half* As, __half* Bs)
{
    const int tid = threadIdx.x, lane = tid & 31, warp = tid >> 5;
    const int wm = (warp & 1) * 64, wn = (warp >> 1) * 32;
    const int KT = K >> 5;
    const int lrow = lane & 15, lsel = (lane >> 4) << 3;

    stage_h(A + (size_t)m0 * K, B + n0, K, N, As, Bs, tid);

    for (int kt = 0; kt < KT; ++kt) {
        int buf = kt & 1;
        if (kt + 1 < KT) {
            stage_h(A + (size_t)m0 * K + (kt + 1) * 32,
                    B + (size_t)(kt + 1) * 32 * N + n0, K, N,
                    As + (buf ^ 1) * AS_SZ, Bs + (buf ^ 1) * BS_SZ, tid);
            asm volatile("cp.async.wait_group 1;\n" ::: "memory");
        } else {
            asm volatile("cp.async.wait_group 0;\n" ::: "memory");
        }
        __syncthreads();
        const __half* Ad = As + buf * AS_SZ;
        const __half* Bd = Bs + buf * BS_SZ;
        #pragma unroll
        for (int kk = 0; kk < 2; ++kk) {
            int kb = kk * 16;
            uint32_t af[4][4], bf[2][4];
            #pragma unroll
            for (int mi = 0; mi < 4; ++mi)
                ldsm4(af[mi][0], af[mi][1], af[mi][2], af[mi][3],
                      sptr(Ad + (wm + mi * 16 + lrow) * LDA + kb + lsel));
            #pragma unroll
            for (int p = 0; p < 2; ++p)
                ldsm4t(bf[p][0], bf[p][1], bf[p][2], bf[p][3],
                       sptr(Bd + (kb + lrow) * LDB + wn + p * 16 + lsel));
            #pragma unroll
            for (int mi = 0; mi < 4; ++mi)
                #pragma unroll
                for (int ni = 0; ni < 4; ++ni)
                    mmaf16(acc[mi][ni][0], acc[mi][ni][1], acc[mi][ni][2], acc[mi][ni][3],
                           af[mi][0], af[mi][1], af[mi][2], af[mi][3],
                           bf[ni >> 1][(ni & 1) * 2], bf[ni >> 1][(ni & 1) * 2 + 1]);
        }
        __syncthreads();
    }
}

// ---------------- QKV: Xh @ W -> scatter half [s,b,h,t,d] --------------------
__global__ __launch_bounds__(256)
void qkv_mma()
{
    __shared__ __half As[2 * AS_SZ];
    __shared__ __half Bs[2 * BS_SZ];
    int z = blockIdx.z; int s = z / 3, p = z - 3 * s;
    const __half* A = g_Xh + (size_t)s * MROWS * EMB;
    const __half* W = (p == 0 ? g_Wqh : (p == 1 ? g_Wkh : g_Wvh)) + (size_t)s * EMB * EMB;
    __half* O = (p == 0 ? g_Q : (p == 1 ? g_K : g_V));
    int m0 = blockIdx.y * 128, n0 = blockIdx.x * 128;

    float acc[4][4][4] = {};
    mainloop_h(A, W, EMB, EMB, m0, n0, acc, As, Bs);

    const int lane = threadIdx.x & 31, warp = threadIdx.x >> 5;
    const int wm = (warp & 1) * 64, wn = (warp >> 1) * 32;
    const int gg = lane >> 2, rr = lane & 3;
    #pragma unroll
    for (int mi = 0; mi < 4; ++mi) {
        int r0 = m0 + wm + mi * 16 + gg;
        #pragma unroll
        for (int ni = 0; ni < 4; ++ni) {
            int c = n0 + wn + ni * 8 + rr * 2;
            int hh = c >> 6, d = c & 63;
            #pragma unroll
            for (int hr = 0; hr < 2; ++hr) {
                int rw = r0 + hr * 8;
                int b = rw >> 9, t = rw & 511;
                size_t dst = ((((size_t)s * 4 + b) * 8 + hh) * 512 + t) * 64 + d;
                __half2 hv = __floats2half2_rn(acc[mi][ni][hr * 2], acc[mi][ni][hr * 2 + 1]);
                *(__half2*)(O + dst) = hv;
            }
        }
    }
}

// ---------------- GEMM + bias + resid -> fp32 ---------------------------------
__global__ __launch_bounds__(256)
void gemm_bias_resid(const __half* __restrict__ Ab, const __half* __restrict__ Bb,
                     const float* __restrict__ biasb, R4 resid,
                     float* __restrict__ Cb, int M, int N, int K)
{
    __shared__ __half As[2 * AS_SZ];
    __shared__ __half Bs[2 * BS_SZ];
    int s = blockIdx.z;
    const __half* A = Ab + (size_t)s * M * K;
    const __half* B = Bb + (size_t)s * K * N;
    const float* bias = biasb + (size_t)s * N;
    const float* R = resid.p[s];
    float* C = Cb + (size_t)s * M * N;
    int m0 = blockIdx.y * 128, n0 = blockIdx.x * 128;

    float acc[4][4][4] = {};
    mainloop_h(A, B, K, N, m0, n0, acc, As, Bs);

    const int lane = threadIdx.x & 31, warp = threadIdx.x >> 5;
    const int wm = (warp & 1) * 64, wn = (warp >> 1) * 32;
    const int gg = lane >> 2, rr = lane & 3;
    #pragma unroll
    for (int mi = 0; mi < 4; ++mi) {
        int r0 = m0 + wm + mi * 16 + gg;
        #pragma unroll
        for (int ni = 0; ni < 4; ++ni) {
            int c = n0 + wn + ni * 8 + rr * 2;
            float bx = bias[c], by = bias[c + 1];
            #pragma unroll
            for (int hr = 0; hr < 2; ++hr) {
                int rw = r0 + hr * 8;
                float2 rv = *(const float2*)(R + (size_t)rw * N + c);
                float v0 = acc[mi][ni][hr * 2 + 0] + bx + rv.x;
                float v1 = acc[mi][ni][hr * 2 + 1] + by + rv.y;
                *(float2*)(C + (size_t)rw * N + c) = make_float2(v0, v1);
            }
        }
    }
}

// ---------------- GEMM + bias + gelu -> fp16 ----------------------------------
__global__ __launch_bounds__(256)
void gemm_bias_gelu(const __half* __restrict__ Ab, const __half* __restrict__ Bb,
                    const float* __restrict__ biasb, __half* __restrict__ Cb,
                    int M, int N, int K)
{
    __shared__ __half As[2 * AS_SZ];
    __shared__ __half Bs[2 * BS_SZ];
    int s = blockIdx.z;
    const __half* A = Ab + (size_t)s * M * K;
    const __half* B = Bb + (size_t)s * K * N;
    const float* bias = biasb + (size_t)s * N;
    __half* C = Cb + (size_t)s * M * N;
    int m0 = blockIdx.y * 128, n0 = blockIdx.x * 128;

    float acc[4][4][4] = {};
    mainloop_h(A, B, K, N, m0, n0, acc, As, Bs);

    const int lane = threadIdx.x & 31, warp = threadIdx.x >> 5;
    const int wm = (warp & 1) * 64, wn = (warp >> 1) * 32;
    const int gg = lane >> 2, rr = lane & 3;
    #pragma unroll
    for (int mi = 0; mi < 4; ++mi) {
        int r0 = m0 + wm + mi * 16 + gg;
        #pragma unroll
        for (int ni = 0; ni < 4; ++ni) {
            int c = n0 + wn + ni * 8 + rr * 2;
            float bx = bias[c], by = bias[c + 1];
            #pragma unroll
            for (int hr = 0; hr < 2; ++hr) {
                int rw = r0 + hr * 8;
                float v0 = gelu_exact(acc[mi][ni][hr * 2 + 0] + bx);
                float v1 = gelu_exact(acc[mi][ni][hr * 2 + 1] + by);
                *(__half2*)(C + (size_t)rw * N + c) = __floats2half2_rn(v0, v1);
            }
        }
    }
}

// ---------------- cross-stream flash attention (fp16 mma, 128-q tiles) --------
// block: 256 thr = 8 warps, each warp 16 q rows. K/V double-buffered.
// smem: Qs[128][72] | Ks[2][64][72] | Vs[2][64][72]  = 55296 B
#define ATTN_SMEM ((128*72 + 2*64*72 + 2*64*72) * 2)
__global__ __launch_bounds__(256, 1)
void attn_h(const float* __restrict__ inter)
{
    extern __shared__ __half asmem[];
    __half* Qs = asmem;                 // [128][72]
    __half* Ks = Qs + 128 * 72;         // [2][64][72]
    __half* Vs = Ks + 2 * 64 * 72;      // [2][64][72]

    const int tid = threadIdx.x, lane = tid & 31, warp = tid >> 5;
    const int qt = blockIdx.x, h = blockIdx.y, ib = blockIdx.z;
    const int i = ib >> 2, b = ib & 3;
    const int gg = lane >> 2, rr = lane & 3;
    const int lrow = lane & 15, lsel = (lane >> 4) << 3;

    const size_t bh = ((size_t)i * 4 + b) * 8 + h;
    const __half* Qg = g_Q + (bh * 512 + qt * 128) * 64;

    // ---- prologue: Q + KV tile0 (group), KV tile1 (group)
    #pragma unroll
    for (int it = 0; it < 4; ++it) {
        int c = tid + it * 256;
        int q = c >> 3, d8 = (c & 7) << 3;
        cpa16(Qs + q * 72 + d8, Qg + q * 64 + d8);
    }
    {
        const __half* Kg = g_K + (((size_t)0 * 4 + b) * 8 + h) * 512 * 64;
        const __half* Vg = g_V + (((size_t)0 * 4 + b) * 8 + h) * 512 * 64;
        #pragma unroll
        for (int it = 0; it < 2; ++it) {
            int c = tid + it * 256;
            int r = c >> 3, d8 = (c & 7) << 3;
            cpa16(Ks + r * 72 + d8, Kg + r * 64 + d8);
            cpa16(Vs + r * 72 + d8, Vg + r * 64 + d8);
        }
        asm volatile("cp.async.commit_group;\n" ::: "memory");
        #pragma unroll
        for (int it = 0; it < 2; ++it) {
            int c = tid + it * 256;
            int r = c >> 3, d8 = (c & 7) << 3;
            cpa16(Ks + 64 * 72 + r * 72 + d8, Kg + (64 + r) * 64 + d8);
            cpa16(Vs + 64 * 72 + r * 72 + d8, Vg + (64 + r) * 64 + d8);
        }
        asm volatile("cp.async.commit_group;\n" ::: "memory");
    }
    asm volatile("cp.async.wait_group 1;\n" ::: "memory");
    __syncthreads();

    uint32_t qf[4][4];
    #pragma unroll
    for (int kf = 0; kf < 4; ++kf)
        ldsm4(qf[kf][0], qf[kf][1], qf[kf][2], qf[kf][3],
              sptr(Qs + (warp * 16 + lrow) * 72 + kf * 16 + lsel));

    float coef[4];
    #pragma unroll
    for (int j = 0; j < 4; ++j) coef[j] = 0.125f * __ldg(inter + i * 4 + j);

    float Of[8][4] = {};
    float Oj[8][4];
    float m0v, m1v, l0, l1;

    for (int tt = 0; tt < 32; ++tt) {
        int j = tt >> 3, kt = tt & 7;
        int buf = tt & 1;
        if (kt == 0) {
            m0v = -1e30f; m1v = -1e30f; l0 = 0.f; l1 = 0.f;
            #pragma unroll
            for (int nf = 0; nf < 8; ++nf)
                Oj[nf][0] = Oj[nf][1] = Oj[nf][2] = Oj[nf][3] = 0.f;
        }
        const __half* Kd = Ks + buf * 64 * 72;
        const __half* Vd = Vs + buf * 64 * 72;

        // S = Q K^T
        float S[8][4] = {};
        #pragma unroll
        for (int nf = 0; nf < 8; ++nf) {
            uint32_t kb[2][4];
            #pragma unroll
            for (int p = 0; p < 2; ++p)
                ldsm4(kb[p][0], kb[p][1], kb[p][2], kb[p][3],
                      sptr(Kd + (nf * 8 + (lane & 7)) * 72 + p * 32 + ((lane >> 3) << 3)));
            #pragma unroll
            for (int kf = 0; kf < 4; ++kf)
                mmaf16(S[nf][0], S[nf][1], S[nf][2], S[nf][3],
                       qf[kf][0], qf[kf][1], qf[kf][2], qf[kf][3],
                       kb[kf >> 1][(kf & 1) * 2], kb[kf >> 1][(kf & 1) * 2 + 1]);
        }

        // online softmax
        float cj = coef[j];
        float mxA = -1e30f, mxB = -1e30f;
        #pragma unroll
        for (int nf = 0; nf < 8; ++nf) {
            S[nf][0] *= cj; S[nf][1] *= cj;
            S[nf][2] *= cj; S[nf][3] *= cj;
            mxA = fmaxf(mxA, fmaxf(S[nf][0], S[nf][1]));
            mxB = fmaxf(mxB, fmaxf(S[nf][2], S[nf][3]));
        }
        mxA = fmaxf(mxA, __shfl_xor_sync(0xffffffffu, mxA, 1));
        mxA = fmaxf(mxA, __shfl_xor_sync(0xffffffffu, mxA, 2));
        mxB = fmaxf(mxB, __shfl_xor_sync(0xffffffffu, mxB, 1));
        mxB = fmaxf(mxB, __shfl_xor_sync(0xffffffffu, mxB, 2));
        float nm0 = fmaxf(m0v, mxA), nm1 = fmaxf(m1v, mxB);
        float al0 = __expf(m0v - nm0), al1 = __expf(m1v - nm1);

        uint32_t pf[4][4];
        float rs0 = 0.f, rs1 = 0.f;
        #pragma unroll
        for (int nf = 0; nf < 8; ++nf) {
            float p0 = __expf(S[nf][0] - nm0), p1 = __expf(S[nf][1] - nm0);
            float p2 = __expf(S[nf][2] - nm1), p3 = __expf(S[nf][3] - nm1);
            rs0 += p0 + p1; rs1 += p2 + p3;
            int kf = nf >> 1;
            if ((nf & 1) == 0) { pf[kf][0] = packh2(p0, p1); pf[kf][1] = packh2(p2, p3); }
            else               { pf[kf][2] = packh2(p0, p1); pf[kf][3] = packh2(p2, p3); }
        }
        rs0 += __shfl_xor_sync(0xffffffffu, rs0, 1);
        rs0 += __shfl_xor_sync(0xffffffffu, rs0, 2);
        rs1 += __shfl_xor_sync(0xffffffffu, rs1, 1);
        rs1 += __shfl_xor_sync(0xffffffffu, rs1, 2);
        l0 = l0 * al0 + rs0; l1 = l1 * al1 + rs1;
        m0v = nm0; m1v = nm1;
        #pragma unroll
        for (int nf = 0; nf < 8; ++nf) {
            Oj[nf][0] *= al0; Oj[nf][1] *= al0;
            Oj[nf][2] *= al1; Oj[nf][3] *= al1;
        }

        // Oj += P @ V
        #pragma unroll
        for (int kf = 0; kf < 4; ++kf) {
            #pragma unroll
            for (int p = 0; p < 4; ++p) {
                uint32_t vb[4];
                ldsm4t(vb[0], vb[1], vb[2], vb[3],
                       sptr(Vd + (kf * 16 + lrow) * 72 + p * 16 + lsel));
                mmaf16(Oj[2 * p][0], Oj[2 * p][1], Oj[2 * p][2], Oj[2 * p][3],
                       pf[kf][0], pf[kf][1], pf[kf][2], pf[kf][3], vb[0], vb[1]);
                mmaf16(Oj[2 * p + 1][0], Oj[2 * p + 1][1], Oj[2 * p + 1][2], Oj[2 * p + 1][3],
                       pf[kf][0], pf[kf][1], pf[kf][2], pf[kf][3], vb[2], vb[3]);
            }
        }

        if (kt == 7) {
            float inv0 = 1.f / l0, inv1 = 1.f / l1;
            #pragma unroll
            for (int nf = 0; nf < 8; ++nf) {
                Of[nf][0] += Oj[nf][0] * inv0; Of[nf][1] += Oj[nf][1] * inv0;
                Of[nf][2] += Oj[nf][2] * inv1; Of[nf][3] += Oj[nf][3] * inv1;
            }
        }

        // pipeline: refill this buffer with tile tt+2, then wait for tt+1
        __syncthreads();
        if (tt + 2 < 32) {
            int nt = tt + 2;
            int nj = nt >> 3, nkt = nt & 7;
            const __half* Kg = g_K + (((size_t)nj * 4 + b) * 8 + h) * 512 * 64
                               + (size_t)nkt * 64 * 64;
            const __half* Vg = g_V + (((size_t)nj * 4 + b) * 8 + h) * 512 * 64
                               + (size_t)nkt * 64 * 64;
            __half* kd = Ks + buf * 64 * 72;
            __half* vd = Vs + buf * 64 * 72;
            #pragma unroll
            for (int it = 0; it < 2; ++it) {
                int c = tid + it * 256;
                int r = c >> 3, d8 = (c & 7) << 3;
                cpa16(kd + r * 72 + d8, Kg + r * 64 + d8);
                cpa16(vd + r * 72 + d8, Vg + r * 64 + d8);
            }
            asm volatile("cp.async.commit_group;\n" ::: "memory");
            asm volatile("cp.async.wait_group 1;\n" ::: "memory");
        } else if (tt + 1 < 32) {
            asm volatile("cp.async.wait_group 0;\n" ::: "memory");
        }
        __syncthreads();
    }

    // transpose via smem (reuse Qs as [64][136]), store to g_MH[i,b,h*64+d, q]
    #pragma unroll
    for (int nf = 0; nf < 8; ++nf) {
        int col = nf * 8 + rr * 2;
        int lq = warp * 16 + gg;
        Qs[col * 136 + lq]           = __float2half(Of[nf][0] * 0.25f);
        Qs[(col + 1) * 136 + lq]     = __float2half(Of[nf][1] * 0.25f);
        Qs[col * 136 + lq + 8]       = __float2half(Of[nf][2] * 0.25f);
        Qs[(col + 1) * 136 + lq + 8] = __float2half(Of[nf][3] * 0.25f);
    }
    __syncthreads();
    __half* Og = g_MH + (((size_t)i * 4 + b) * 512 + h * 64) * 512 + qt * 128;
    #pragma unroll
    for (int it = 0; it < 4; ++it) {
        int c = tid + it * 256;
        int d = c >> 4, q8 = (c & 15) << 3;
        *(uint4*)(Og + (size_t)d * 512 + q8) = *(const uint4*)(Qs + d * 136 + q8);
    }
}

// ---------------- row LayerNorm over E=512 -------------------------------------
__global__ __launch_bounds__(128)
void ln_kernel(const float* __restrict__ in, const float* __restrict__ gw,
               const float* __restrict__ bw, float* __restrict__ out,
               __half* __restrict__ outh)
{
    int row = blockIdx.x;
    int s = row >> 11;
    int t = threadIdx.x;

    float4 xv = ((const float4*)(in + (size_t)row * 512))[t];
    float sum = xv.x + xv.y + xv.z + xv.w;
    float sq  = xv.x * xv.x + xv.y * xv.y + xv.z * xv.z + xv.w * xv.w;
    #pragma unroll
    for (int off = 16; off >= 1; off >>= 1) {
        sum += __shfl_xor_sync(0xffffffffu, sum, off);
        sq  += __shfl_xor_sync(0xffffffffu, sq,  off);
    }
    __shared__ float s_sum[4], s_sq[4];
    int w = t >> 5, lane = t & 31;
    if (lane == 0) { s_sum[w] = sum; s_sq[w] = sq; }
    __syncthreads();
    sum = s_sum[0] + s_sum[1] + s_sum[2] + s_sum[3];
    sq  = s_sq[0]  + s_sq[1]  + s_sq[2]  + s_sq[3];

    float mean = sum * (1.0f / 512.0f);
    float var  = sq  * (1.0f / 512.0f) - mean * mean;
    float inv  = rsqrtf(var + 1e-5f);

    float4 g4 = ((const float4*)(gw + s * 512))[t];
    float4 b4 = ((const float4*)(bw + s * 512))[t];
    float4 o;
    o.x = (xv.x - mean) * inv * g4.x + b4.x;
    o.y = (xv.y - mean) * inv * g4.y + b4.y;
    o.z = (xv.z - mean) * inv * g4.z + b4.z;
    o.w = (xv.w - mean) * inv * g4.w + b4.w;
    ((float4*)(out + (size_t)row * 512))[t] = o;
    if (outh) {
        ((__half2*)(outh + (size_t)row * 512))[t * 2]     = __floats2half2_rn(o.x, o.y);
        ((__half2*)(outh + (size_t)row * 512))[t * 2 + 1] = __floats2half2_rn(o.z, o.w);
    }
}

// ---------------- launch --------------------------------------------------------
extern "C" void kernel_launch(void* const* d_in, const int* in_sizes, int n_in,
                              void* d_out, int out_size)
{
    const float* xs0 = (const float*)d_in[0];
    const float* xs1 = (const float*)d_in[1];
    const float* xs2 = (const float*)d_in[2];
    const float* xs3 = (const float*)d_in[3];
    const float* Wq  = (const float*)d_in[4];
    const float* Wk  = (const float*)d_in[5];
    const float* Wv  = (const float*)d_in[6];
    const float* Wo  = (const float*)d_in[7];
    const float* bo  = (const float*)d_in[8];
    const float* ln1g = (const float*)d_in[9];
    const float* ln1b = (const float*)d_in[10];
    const float* ln2g = (const float*)d_in[11];
    const float* ln2b = (const float*)d_in[12];
    const float* W1  = (const float*)d_in[13];
    const float* bf1 = (const float*)d_in[14];
    const float* W2  = (const float*)d_in[15];
    const float* bf2 = (const float*)d_in[16];
    const float* inter = (const float*)d_in[17];

    __half *wq, *wo, *w1, *w2, *mh, *hb, *r1h;
    float *t1, *r1, *t2;
    cudaGetSymbolAddress((void**)&wq,  g_Wqh);
    cudaGetSymbolAddress((void**)&wo,  g_Woh);
    cudaGetSymbolAddress((void**)&w1,  g_W1h);
    cudaGetSymbolAddress((void**)&w2,  g_W2h);
    cudaGetSymbolAddress((void**)&mh,  g_MH);
    cudaGetSymbolAddress((void**)&hb,  g_HB);
    cudaGetSymbolAddress((void**)&r1h, g_R1h);
    cudaGetSymbolAddress((void**)&t1,  g_T1);
    cudaGetSymbolAddress((void**)&r1,  g_R1);
    cudaGetSymbolAddress((void**)&t2,  g_T2);

    cudaFuncSetAttribute(attn_h, cudaFuncAttributeMaxDynamicSharedMemorySize, ATTN_SMEM);

    const int NW = 4 * 512 * 512;
    const int NF = 4 * 512 * 2048;
    cvt4_kernel<<<dim3(NW / 1024, 4), 256>>>(Wq, Wk, Wv, Wo);
    cvt2_kernel<<<dim3(NF / 1024, 2), 256>>>(W1, W2);
    xcvt_kernel<<<dim3(1024, 4), 256>>>(xs0, xs1, xs2, xs3);

    // QKV projections (fp16 in/out)
    qkv_mma<<<dim3(4, 16, 12), 256>>>();

    // cross-stream attention (128-row q tiles, double-buffered K/V)
    attn_h<<<dim3(4, 8, 16), 256, ATTN_SMEM>>>(inter);

    // T1 = MH @ Wo + bo + x
    R4 rx; rx.p[0] = xs0; rx.p[1] = xs1; rx.p[2] = xs2; rx.p[3] = xs3;
    gemm_bias_resid<<<dim3(4, 16, 4), 256>>>(mh, wo, bo, rx, t1, MROWS, EMB, EMB);

    // R1 = LN1(T1)  (fp32 + fp16 copies)
    ln_kernel<<<8192, 128>>>(t1, ln1g, ln1b, r1, r1h);

    // HB = gelu(R1h @ W1 + bf1)  (fp16 out)
    gemm_bias_gelu<<<dim3(16, 16, 4), 256>>>(r1h, w1, bf1, hb, MROWS, 4 * EMB, EMB);

    // T2 = HB @ W2 + bf2 + R1
    R4 rr; for (int s = 0; s < 4; ++s) rr.p[s] = r1 + (size_t)s * MROWS * EMB;
    gemm_bias_resid<<<dim3(4, 16, 4), 256>>>(hb, w2, bf2, rr, t2, MROWS, EMB, 2048);

    // out = LN2(T2)
    ln_kernel<<<8192, 128>>>(t2, ln2g, ln2b, (float*)d_out, nullptr);
}

// round 6
// speedup vs baseline: 1.0191x; 1.0191x over previous
#include <cuda_runtime.h>
#include <cuda_fp16.h>
#include <math.h>
#include <stdint.h>

#define MROWS 2048
#define EMB   512

// ---------------- scratch (device globals) -----------------------------------
__device__ float  g_T1 [4UL*2048*512];
__device__ float  g_R1 [4UL*2048*512];
__device__ float  g_T2 [4UL*2048*512];
__device__ __half g_Xh [4UL*2048*512];
__device__ __half g_Q  [4UL*2048*512];   // [s,b,h,t,d]
__device__ __half g_K  [4UL*2048*512];
__device__ __half g_V  [4UL*2048*512];
__device__ __half g_MH [4UL*2048*512];   // pre-transposed attention out
__device__ __half g_R1h[4UL*2048*512];
__device__ __half g_HB [4UL*2048*2048];
__device__ __half g_Wqh[4UL*512*512];
__device__ __half g_Wkh[4UL*512*512];
__device__ __half g_Wvh[4UL*512*512];
__device__ __half g_Woh[4UL*512*512];
__device__ __half g_W1h[4UL*512*2048];
__device__ __half g_W2h[4UL*2048*512];

struct R4 { const float* p[4]; };

__device__ __forceinline__ float gelu_exact(float x) {
    return 0.5f * x * (1.0f + erff(x * 0.70710678118654752440f));
}
__device__ __forceinline__ uint32_t sptr(const void* p) {
    return (uint32_t)__cvta_generic_to_shared(p);
}
__device__ __forceinline__ void cpa16(void* s, const void* g) {
    asm volatile("cp.async.cg.shared.global [%0],[%1],16;\n" :: "r"(sptr(s)), "l"(g));
}
__device__ __forceinline__ void ldsm4(uint32_t& r0, uint32_t& r1, uint32_t& r2,
                                      uint32_t& r3, uint32_t a) {
    asm volatile("ldmatrix.sync.aligned.m8n8.x4.shared.b16 {%0,%1,%2,%3},[%4];\n"
        : "=r"(r0), "=r"(r1), "=r"(r2), "=r"(r3) : "r"(a));
}
__device__ __forceinline__ void ldsm4t(uint32_t& r0, uint32_t& r1, uint32_t& r2,
                                       uint32_t& r3, uint32_t a) {
    asm volatile("ldmatrix.sync.aligned.m8n8.x4.trans.shared.b16 {%0,%1,%2,%3},[%4];\n"
        : "=r"(r0), "=r"(r1), "=r"(r2), "=r"(r3) : "r"(a));
}
__device__ __forceinline__ void mmaf16(float& d0, float& d1, float& d2, float& d3,
    uint32_t a0, uint32_t a1, uint32_t a2, uint32_t a3, uint32_t b0, uint32_t b1) {
    asm volatile("mma.sync.aligned.m16n8k16.row.col.f32.f16.f16.f32 "
        "{%0,%1,%2,%3},{%4,%5,%6,%7},{%8,%9},{%0,%1,%2,%3};\n"
        : "+f"(d0), "+f"(d1), "+f"(d2), "+f"(d3)
        : "r"(a0), "r"(a1), "r"(a2), "r"(a3), "r"(b0), "r"(b1));
}
__device__ __forceinline__ uint32_t packh2(float x, float y) {
    __half2 h = __floats2half2_rn(x, y);
    return *(uint32_t*)&h;
}

// ---------------- batched fp32->fp16 converters --------------------------------
__global__ __launch_bounds__(256)
void cvt4_kernel(const float* w0, const float* w1, const float* w2, const float* w3)
{
    int wsel = blockIdx.y;
    const float* s = wsel == 0 ? w0 : wsel == 1 ? w1 : wsel == 2 ? w2 : w3;
    __half* d = wsel == 0 ? g_Wqh : wsel == 1 ? g_Wkh : wsel == 2 ? g_Wvh : g_Woh;
    int i = (blockIdx.x * 256 + threadIdx.x) * 4;
    float4 v = *(const float4*)(s + i);
    *(__half2*)(d + i)     = __floats2half2_rn(v.x, v.y);
    *(__half2*)(d + i + 2) = __floats2half2_rn(v.z, v.w);
}
__global__ __launch_bounds__(256)
void cvt2_kernel(const float* w1, const float* w2)
{
    const float* s = blockIdx.y == 0 ? w1 : w2;
    __half* d = blockIdx.y == 0 ? g_W1h : g_W2h;
    int i = (blockIdx.x * 256 + threadIdx.x) * 4;
    float4 v = *(const float4*)(s + i);
    *(__half2*)(d + i)     = __floats2half2_rn(v.x, v.y);
    *(__half2*)(d + i + 2) = __floats2half2_rn(v.z, v.w);
}
__global__ __launch_bounds__(256)
void xcvt_kernel(const float* __restrict__ x0, const float* __restrict__ x1,
                 const float* __restrict__ x2, const float* __restrict__ x3) {
    int s = blockIdx.y;
    const float* x = s == 0 ? x0 : s == 1 ? x1 : s == 2 ? x2 : x3;
    int i = (blockIdx.x * 256 + threadIdx.x) * 4;
    float4 v = *(const float4*)(x + i);
    __half* d = g_Xh + (size_t)s * MROWS * EMB + i;
    *(__half2*)(d)     = __floats2half2_rn(v.x, v.y);
    *(__half2*)(d + 2) = __floats2half2_rn(v.z, v.w);
}

// ---------------- fp16 MMA GEMM core: 128x128x32, 256 thr, 3-stage -------------
#define LDA 40
#define LDB 152
#define AS_SZ (128*LDA)
#define BS_SZ (32*LDB)
#define GEMM_SMEM3 (3 * (AS_SZ + BS_SZ) * 2)

__device__ __forceinline__ void stage_h(const __half* Ag, const __half* Bg,
    int K, int N, __half* Ad, __half* Bd, int tid)
{
    #pragma unroll
    for (int i = 0; i < 2; ++i) {
        int c = tid + (i << 8);
        int ar = c >> 2, ac = (c & 3) << 3;
        cpa16(Ad + ar * LDA + ac, Ag + (size_t)ar * K + ac);
        int br = c >> 4, bn = (c & 15) << 3;
        cpa16(Bd + br * LDB + bn, Bg + (size_t)br * N + bn);
    }
    asm volatile("cp.async.commit_group;\n" ::: "memory");
}

__device__ __forceinline__ void mainloop_h(
    const __half* __restrict__ A, const __half* __restrict__ B,
    int K, int N, int m0, int n0, float (&acc)[4][4][4],
    __half* As, __half* Bs)
{
    const int tid = threadIdx.x, lane = tid & 31, warp = tid >> 5;
    const int wm = (warp & 1) * 64, wn = (warp >> 1) * 32;
    const int KT = K >> 5;
    const int lrow = lane & 15, lsel = (lane >> 4) << 3;

    // prologue: tiles 0 and 1
    stage_h(A + (size_t)m0 * K, B + n0, K, N, As, Bs, tid);
    stage_h(A + (size_t)m0 * K + 32, B + (size_t)32 * N + n0, K, N,
            As + AS_SZ, Bs + BS_SZ, tid);

    for (int kt = 0; kt < KT; ++kt) {
        int buf = kt % 3;
        if (kt + 1 < KT)
            asm volatile("cp.async.wait_group 1;\n" ::: "memory");
        else
            asm volatile("cp.async.wait_group 0;\n" ::: "memory");
        __syncthreads();

        const __half* Ad = As + buf * AS_SZ;
        const __half* Bd = Bs + buf * BS_SZ;
        #pragma unroll
        for (int kk = 0; kk < 2; ++kk) {
            int kb = kk * 16;
            uint32_t af[4][4], bf[2][4];
            #pragma unroll
            for (int mi = 0; mi < 4; ++mi)
                ldsm4(af[mi][0], af[mi][1], af[mi][2], af[mi][3],
                      sptr(Ad + (wm + mi * 16 + lrow) * LDA + kb + lsel));
            #pragma unroll
            for (int p = 0; p < 2; ++p)
                ldsm4t(bf[p][0], bf[p][1], bf[p][2], bf[p][3],
                       sptr(Bd + (kb + lrow) * LDB + wn + p * 16 + lsel));
            #pragma unroll
            for (int mi = 0; mi < 4; ++mi)
                #pragma unroll
                for (int ni = 0; ni < 4; ++ni)
                    mmaf16(acc[mi][ni][0], acc[mi][ni][1], acc[mi][ni][2], acc[mi][ni][3],
                           af[mi][0], af[mi][1], af[mi][2], af[mi][3],
                           bf[ni >> 1][(ni & 1) * 2], bf[ni >> 1][(ni & 1) * 2 + 1]);
        }
        // issue next stage (buffer (kt+2)%3 == (kt-1)%3, safe: all warps passed barrier)
        if (kt + 2 < KT) {
            int nb = (kt + 2) % 3;
            stage_h(A + (size_t)m0 * K + (kt + 2) * 32,
                    B + (size_t)(kt + 2) * 32 * N + n0, K, N,
                    As + nb * AS_SZ, Bs + nb * BS_SZ, tid);
        }
    }
    __syncthreads();
}

// ---------------- QKV: Xh @ W -> scatter half [s,b,h,t,d] --------------------
__global__ __launch_bounds__(256)
void qkv_mma()
{
    extern __shared__ __half gsm[];
    __half* As = gsm; __half* Bs = gsm + 3 * AS_SZ;
    int z = blockIdx.z; int s = z / 3, p = z - 3 * s;
    const __half* A = g_Xh + (size_t)s * MROWS * EMB;
    const __half* W = (p == 0 ? g_Wqh : (p == 1 ? g_Wkh : g_Wvh)) + (size_t)s * EMB * EMB;
    __half* O = (p == 0 ? g_Q : (p == 1 ? g_K : g_V));
    int m0 = blockIdx.y * 128, n0 = blockIdx.x * 128;

    float acc[4][4][4] = {};
    mainloop_h(A, W, EMB, EMB, m0, n0, acc, As, Bs);

    const int lane = threadIdx.x & 31, warp = threadIdx.x >> 5;
    const int wm = (warp & 1) * 64, wn = (warp >> 1) * 32;
    const int gg = lane >> 2, rr = lane & 3;
    #pragma unroll
    for (int mi = 0; mi < 4; ++mi) {
        int r0 = m0 + wm + mi * 16 + gg;
        #pragma unroll
        for (int ni = 0; ni < 4; ++ni) {
            int c = n0 + wn + ni * 8 + rr * 2;
            int hh = c >> 6, d = c & 63;
            #pragma unroll
            for (int hr = 0; hr < 2; ++hr) {
                int rw = r0 + hr * 8;
                int b = rw >> 9, t = rw & 511;
                size_t dst = ((((size_t)s * 4 + b) * 8 + hh) * 512 + t) * 64 + d;
                __half2 hv = __floats2half2_rn(acc[mi][ni][hr * 2], acc[mi][ni][hr * 2 + 1]);
                *(__half2*)(O + dst) = hv;
            }
        }
    }
}

// ---------------- GEMM + bias + resid -> fp32 ---------------------------------
__global__ __launch_bounds__(256)
void gemm_bias_resid(const __half* __restrict__ Ab, const __half* __restrict__ Bb,
                     const float* __restrict__ biasb, R4 resid,
                     float* __restrict__ Cb, int M, int N, int K)
{
    extern __shared__ __half gsm[];
    __half* As = gsm; __half* Bs = gsm + 3 * AS_SZ;
    int s = blockIdx.z;
    const __half* A = Ab + (size_t)s * M * K;
    const __half* B = Bb + (size_t)s * K * N;
    const float* bias = biasb + (size_t)s * N;
    const float* R = resid.p[s];
    float* C = Cb + (size_t)s * M * N;
    int m0 = blockIdx.y * 128, n0 = blockIdx.x * 128;

    float acc[4][4][4] = {};
    mainloop_h(A, B, K, N, m0, n0, acc, As, Bs);

    const int lane = threadIdx.x & 31, warp = threadIdx.x >> 5;
    const int wm = (warp & 1) * 64, wn = (warp >> 1) * 32;
    const int gg = lane >> 2, rr = lane & 3;
    #pragma unroll
    for (int mi = 0; mi < 4; ++mi) {
        int r0 = m0 + wm + mi * 16 + gg;
        #pragma unroll
        for (int ni = 0; ni < 4; ++ni) {
            int c = n0 + wn + ni * 8 + rr * 2;
            float bx = bias[c], by = bias[c + 1];
            #pragma unroll
            for (int hr = 0; hr < 2; ++hr) {
                int rw = r0 + hr * 8;
                float2 rv = *(const float2*)(R + (size_t)rw * N + c);
                float v0 = acc[mi][ni][hr * 2 + 0] + bx + rv.x;
                float v1 = acc[mi][ni][hr * 2 + 1] + by + rv.y;
                *(float2*)(C + (size_t)rw * N + c) = make_float2(v0, v1);
            }
        }
    }
}

// ---------------- GEMM + bias + gelu -> fp16 ----------------------------------
__global__ __launch_bounds__(256)
void gemm_bias_gelu(const __half* __restrict__ Ab, const __half* __restrict__ Bb,
                    const float* __restrict__ biasb, __half* __restrict__ Cb,
                    int M, int N, int K)
{
    extern __shared__ __half gsm[];
    __half* As = gsm; __half* Bs = gsm + 3 * AS_SZ;
    int s = blockIdx.z;
    const __half* A = Ab + (size_t)s * M * K;
    const __half* B = Bb + (size_t)s * K * N;
    const float* bias = biasb + (size_t)s * N;
    __half* C = Cb + (size_t)s * M * N;
    int m0 = blockIdx.y * 128, n0 = blockIdx.x * 128;

    float acc[4][4][4] = {};
    mainloop_h(A, B, K, N, m0, n0, acc, As, Bs);

    const int lane = threadIdx.x & 31, warp = threadIdx.x >> 5;
    const int wm = (warp & 1) * 64, wn = (warp >> 1) * 32;
    const int gg = lane >> 2, rr = lane & 3;
    #pragma unroll
    for (int mi = 0; mi < 4; ++mi) {
        int r0 = m0 + wm + mi * 16 + gg;
        #pragma unroll
        for (int ni = 0; ni < 4; ++ni) {
            int c = n0 + wn + ni * 8 + rr * 2;
            float bx = bias[c], by = bias[c + 1];
            #pragma unroll
            for (int hr = 0; hr < 2; ++hr) {
                int rw = r0 + hr * 8;
                float v0 = gelu_exact(acc[mi][ni][hr * 2 + 0] + bx);
                float v1 = gelu_exact(acc[mi][ni][hr * 2 + 1] + by);
                *(__half2*)(C + (size_t)rw * N + c) = __floats2half2_rn(v0, v1);
            }
        }
    }
}

// ---------------- cross-stream flash attention (fp16 mma, 3-stage KV) ----------
// block: 64 q rows, 128 thr = 4 warps x 16 q rows. smem: Q[64][72] + 3x(K,V)[64][72]
#define ATTN_SMEM3 ((64*72 + 3*2*64*72) * 2)
__global__ __launch_bounds__(128)
void attn_h(const float* __restrict__ inter)
{
    extern __shared__ __half asmem[];
    __half* Qs = asmem;                  // [64][72]
    __half* KV = Qs + 64 * 72;           // 3 stages x (K[64][72], V[64][72])

    const int tid = threadIdx.x, lane = tid & 31, warp = tid >> 5;
    const int qt = blockIdx.x, h = blockIdx.y, ib = blockIdx.z;
    const int i = ib >> 2, b = ib & 3;
    const int gg = lane >> 2, rr = lane & 3;
    const int lrow = lane & 15, lsel = (lane >> 4) << 3;

    const __half* Qg = g_Q + ((((size_t)i * 4 + b) * 8 + h) * 512 + qt * 64) * 64;
    const size_t kvstride = (size_t)4 * 8 * 512 * 64;  // j stride in g_K/g_V
    const size_t bhoff = (((size_t)b) * 8 + h) * 512 * 64;

    // Q load (synchronous-ish: folded into first wait)
    #pragma unroll
    for (int it = 0; it < 4; ++it) {
        int c = tid + it * 128;
        int q = c >> 3, d8 = (c & 7) << 3;
        cpa16(Qs + q * 72 + d8, Qg + q * 64 + d8);
    }
    asm volatile("cp.async.commit_group;\ncp.async.wait_group 0;\n" ::: "memory");
    __syncthreads();

    uint32_t qf[4][4];
    #pragma unroll
    for (int kf = 0; kf < 4; ++kf)
        ldsm4(qf[kf][0], qf[kf][1], qf[kf][2], qf[kf][3],
              sptr(Qs + (warp * 16 + lrow) * 72 + kf * 16 + lsel));

    // prologue: tiles 0, 1
    #pragma unroll
    for (int pt = 0; pt < 2; ++pt) {
        const __half* Kg = g_K + bhoff + (size_t)pt * 64 * 64;   // j=0, kt=pt
        const __half* Vg = g_V + bhoff + (size_t)pt * 64 * 64;
        __half* kd = KV + pt * 2 * 64 * 72;
        __half* vd = kd + 64 * 72;
        #pragma unroll
        for (int it = 0; it < 4; ++it) {
            int c = tid + it * 128;
            int r = c >> 3, d8 = (c & 7) << 3;
            cpa16(kd + r * 72 + d8, Kg + r * 64 + d8);
            cpa16(vd + r * 72 + d8, Vg + r * 64 + d8);
        }
        asm volatile("cp.async.commit_group;\n" ::: "memory");
    }

    float coef[4];
    #pragma unroll
    for (int j = 0; j < 4; ++j) coef[j] = 0.125f * __ldg(inter + i * 4 + j);

    float Of[8][4] = {};
    float Oj[8][4];
    float m0v, m1v, l0, l1;

    for (int tt = 0; tt < 32; ++tt) {
        int j = tt >> 3, kt = tt & 7;
        int buf = tt % 3;
        if (kt == 0) {
            m0v = -1e30f; m1v = -1e30f; l0 = 0.f; l1 = 0.f;
            #pragma unroll
            for (int nf = 0; nf < 8; ++nf)
                Oj[nf][0] = Oj[nf][1] = Oj[nf][2] = Oj[nf][3] = 0.f;
        }
        if (tt + 1 < 32)
            asm volatile("cp.async.wait_group 1;\n" ::: "memory");
        else
            asm volatile("cp.async.wait_group 0;\n" ::: "memory");
        __syncthreads();

        const __half* Kd = KV + buf * 2 * 64 * 72;
        const __half* Vd = Kd + 64 * 72;

        // S = Q K^T
        float S[8][4] = {};
        #pragma unroll
        for (int nf = 0; nf < 8; ++nf) {
            uint32_t kb[2][4];
            #pragma unroll
            for (int p = 0; p < 2; ++p)
                ldsm4(kb[p][0], kb[p][1], kb[p][2], kb[p][3],
                      sptr(Kd + (nf * 8 + (lane & 7)) * 72 + p * 32 + ((lane >> 3) << 3)));
            #pragma unroll
            for (int kf = 0; kf < 4; ++kf)
                mmaf16(S[nf][0], S[nf][1], S[nf][2], S[nf][3],
                       qf[kf][0], qf[kf][1], qf[kf][2], qf[kf][3],
                       kb[kf >> 1][(kf & 1) * 2], kb[kf >> 1][(kf & 1) * 2 + 1]);
        }

        // issue load of tile tt+2 into buffer (tt+2)%3 (== (tt-1)%3, safe)
        if (tt + 2 < 32) {
            int nt = tt + 2;
            int nj = nt >> 3, nkt = nt & 7;
            const __half* Kg = g_K + (size_t)nj * kvstride + bhoff + (size_t)nkt * 64 * 64;
            const __half* Vg = g_V + (size_t)nj * kvstride + bhoff + (size_t)nkt * 64 * 64;
            __half* kd = KV + ((tt + 2) % 3) * 2 * 64 * 72;
            __half* vd = kd + 64 * 72;
            #pragma unroll
            for (int it = 0; it < 4; ++it) {
                int c = tid + it * 128;
                int r = c >> 3, d8 = (c & 7) << 3;
                cpa16(kd + r * 72 + d8, Kg + r * 64 + d8);
                cpa16(vd + r * 72 + d8, Vg + r * 64 + d8);
            }
            asm volatile("cp.async.commit_group;\n" ::: "memory");
        }

        // online softmax
        float cj = coef[j];
        float mxA = -1e30f, mxB = -1e30f;
        #pragma unroll
        for (int nf = 0; nf < 8; ++nf) {
            S[nf][0] *= cj; S[nf][1] *= cj;
            S[nf][2] *= cj; S[nf][3] *= cj;
            mxA = fmaxf(mxA, fmaxf(S[nf][0], S[nf][1]));
            mxB = fmaxf(mxB, fmaxf(S[nf][2], S[nf][3]));
        }
        mxA = fmaxf(mxA, __shfl_xor_sync(0xffffffffu, mxA, 1));
        mxA = fmaxf(mxA, __shfl_xor_sync(0xffffffffu, mxA, 2));
        mxB = fmaxf(mxB, __shfl_xor_sync(0xffffffffu, mxB, 1));
        mxB = fmaxf(mxB, __shfl_xor_sync(0xffffffffu, mxB, 2));
        float nm0 = fmaxf(m0v, mxA), nm1 = fmaxf(m1v, mxB);
        float al0 = __expf(m0v - nm0), al1 = __expf(m1v - nm1);

        uint32_t pf[4][4];
        float rs0 = 0.f, rs1 = 0.f;
        #pragma unroll
        for (int nf = 0; nf < 8; ++nf) {
            float p0 = __expf(S[nf][0] - nm0), p1 = __expf(S[nf][1] - nm0);
            float p2 = __expf(S[nf][2] - nm1), p3 = __expf(S[nf][3] - nm1);
            rs0 += p0 + p1; rs1 += p2 + p3;
            int kf = nf >> 1;
            if ((nf & 1) == 0) { pf[kf][0] = packh2(p0, p1); pf[kf][1] = packh2(p2, p3); }
            else               { pf[kf][2] = packh2(p0, p1); pf[kf][3] = packh2(p2, p3); }
        }
        rs0 += __shfl_xor_sync(0xffffffffu, rs0, 1);
        rs0 += __shfl_xor_sync(0xffffffffu, rs0, 2);
        rs1 += __shfl_xor_sync(0xffffffffu, rs1, 1);
        rs1 += __shfl_xor_sync(0xffffffffu, rs1, 2);
        l0 = l0 * al0 + rs0; l1 = l1 * al1 + rs1;
        m0v = nm0; m1v = nm1;
        #pragma unroll
        for (int nf = 0; nf < 8; ++nf) {
            Oj[nf][0] *= al0; Oj[nf][1] *= al0;
            Oj[nf][2] *= al1; Oj[nf][3] *= al1;
        }

        // Oj += P @ V
        #pragma unroll
        for (int kf = 0; kf < 4; ++kf) {
            #pragma unroll
            for (int p = 0; p < 4; ++p) {
                uint32_t vb[4];
                ldsm4t(vb[0], vb[1], vb[2], vb[3],
                       sptr(Vd + (kf * 16 + lrow) * 72 + p * 16 + lsel));
                mmaf16(Oj[2 * p][0], Oj[2 * p][1], Oj[2 * p][2], Oj[2 * p][3],
                       pf[kf][0], pf[kf][1], pf[kf][2], pf[kf][3], vb[0], vb[1]);
                mmaf16(Oj[2 * p + 1][0], Oj[2 * p + 1][1], Oj[2 * p + 1][2], Oj[2 * p + 1][3],
                       pf[kf][0], pf[kf][1], pf[kf][2], pf[kf][3], vb[2], vb[3]);
            }
        }

        if (kt == 7) {
            float inv0 = 1.f / l0, inv1 = 1.f / l1;
            #pragma unroll
            for (int nf = 0; nf < 8; ++nf) {
                Of[nf][0] += Oj[nf][0] * inv0; Of[nf][1] += Oj[nf][1] * inv0;
                Of[nf][2] += Oj[nf][2] * inv1; Of[nf][3] += Oj[nf][3] * inv1;
            }
        }
    }

    // transpose via smem (reuse Qs), store half to g_MH[i,b, h*64+d, q]
    __syncthreads();
    #pragma unroll
    for (int nf = 0; nf < 8; ++nf) {
        int col = nf * 8 + rr * 2;
        int lq = warp * 16 + gg;
        Qs[col * 72 + lq]           = __float2half(Of[nf][0] * 0.25f);
        Qs[(col + 1) * 72 + lq]     = __float2half(Of[nf][1] * 0.25f);
        Qs[col * 72 + lq + 8]       = __float2half(Of[nf][2] * 0.25f);
        Qs[(col + 1) * 72 + lq + 8] = __float2half(Of[nf][3] * 0.25f);
    }
    __syncthreads();
    __half* Og = g_MH + (((size_t)i * 4 + b) * 512 + h * 64) * 512 + qt * 64;
    #pragma unroll
    for (int it = 0; it < 4; ++it) {
        int c = tid + it * 128;
        int d = c >> 3, q8 = (c & 7) << 3;
        *(uint4*)(Og + (size_t)d * 512 + q8) = *(const uint4*)(Qs + d * 72 + q8);
    }
}

// ---------------- row LayerNorm over E=512 -------------------------------------
__global__ __launch_bounds__(128)
void ln_kernel(const float* __restrict__ in, const float* __restrict__ gw,
               const float* __restrict__ bw, float* __restrict__ out,
               __half* __restrict__ outh)
{
    int row = blockIdx.x;
    int s = row >> 11;
    int t = threadIdx.x;

    float4 xv = ((const float4*)(in + (size_t)row * 512))[t];
    float sum = xv.x + xv.y + xv.z + xv.w;
    float sq  = xv.x * xv.x + xv.y * xv.y + xv.z * xv.z + xv.w * xv.w;
    #pragma unroll
    for (int off = 16; off >= 1; off >>= 1) {
        sum += __shfl_xor_sync(0xffffffffu, sum, off);
        sq  += __shfl_xor_sync(0xffffffffu, sq,  off);
    }
    __shared__ float s_sum[4], s_sq[4];
    int w = t >> 5, lane = t & 31;
    if (lane == 0) { s_sum[w] = sum; s_sq[w] = sq; }
    __syncthreads();
    sum = s_sum[0] + s_sum[1] + s_sum[2] + s_sum[3];
    sq  = s_sq[0]  + s_sq[1]  + s_sq[2]  + s_sq[3];

    float mean = sum * (1.0f / 512.0f);
    float var  = sq  * (1.0f / 512.0f) - mean * mean;
    float inv  = rsqrtf(var + 1e-5f);

    float4 g4 = ((const float4*)(gw + s * 512))[t];
    float4 b4 = ((const float4*)(bw + s * 512))[t];
    float4 o;
    o.x = (xv.x - mean) * inv * g4.x + b4.x;
    o.y = (xv.y - mean) * inv * g4.y + b4.y;
    o.z = (xv.z - mean) * inv * g4.z + b4.z;
    o.w = (xv.w - mean) * inv * g4.w + b4.w;
    ((float4*)(out + (size_t)row * 512))[t] = o;
    if (outh) {
        ((__half2*)(outh + (size_t)row * 512))[t * 2]     = __floats2half2_rn(o.x, o.y);
        ((__half2*)(outh + (size_t)row * 512))[t * 2 + 1] = __floats2half2_rn(o.z, o.w);
    }
}

// ---------------- launch --------------------------------------------------------
extern "C" void kernel_launch(void* const* d_in, const int* in_sizes, int n_in,
                              void* d_out, int out_size)
{
    const float* xs0 = (const float*)d_in[0];
    const float* xs1 = (const float*)d_in[1];
    const float* xs2 = (const float*)d_in[2];
    const float* xs3 = (const float*)d_in[3];
    const float* Wq  = (const float*)d_in[4];
    const float* Wk  = (const float*)d_in[5];
    const float* Wv  = (const float*)d_in[6];
    const float* Wo  = (const float*)d_in[7];
    const float* bo  = (const float*)d_in[8];
    const float* ln1g = (const float*)d_in[9];
    const float* ln1b = (const float*)d_in[10];
    const float* ln2g = (const float*)d_in[11];
    const float* ln2b = (const float*)d_in[12];
    const float* W1  = (const float*)d_in[13];
    const float* bf1 = (const float*)d_in[14];
    const float* W2  = (const float*)d_in[15];
    const float* bf2 = (const float*)d_in[16];
    const float* inter = (const float*)d_in[17];

    __half *wq, *wo, *w1, *w2, *mh, *hb, *r1h;
    float *t1, *r1, *t2;
    cudaGetSymbolAddress((void**)&wq,  g_Wqh);
    cudaGetSymbolAddress((void**)&wo,  g_Woh);
    cudaGetSymbolAddress((void**)&w1,  g_W1h);
    cudaGetSymbolAddress((void**)&w2,  g_W2h);
    cudaGetSymbolAddress((void**)&mh,  g_MH);
    cudaGetSymbolAddress((void**)&hb,  g_HB);
    cudaGetSymbolAddress((void**)&r1h, g_R1h);
    cudaGetSymbolAddress((void**)&t1,  g_T1);
    cudaGetSymbolAddress((void**)&r1,  g_R1);
    cudaGetSymbolAddress((void**)&t2,  g_T2);

    cudaFuncSetAttribute(qkv_mma, cudaFuncAttributeMaxDynamicSharedMemorySize, GEMM_SMEM3);
    cudaFuncSetAttribute(gemm_bias_resid, cudaFuncAttributeMaxDynamicSharedMemorySize, GEMM_SMEM3);
    cudaFuncSetAttribute(gemm_bias_gelu, cudaFuncAttributeMaxDynamicSharedMemorySize, GEMM_SMEM3);
    cudaFuncSetAttribute(attn_h, cudaFuncAttributeMaxDynamicSharedMemorySize, ATTN_SMEM3);

    const int NW = 4 * 512 * 512;
    const int NF = 4 * 512 * 2048;
    cvt4_kernel<<<dim3(NW / 1024, 4), 256>>>(Wq, Wk, Wv, Wo);
    cvt2_kernel<<<dim3(NF / 1024, 2), 256>>>(W1, W2);
    xcvt_kernel<<<dim3(1024, 4), 256>>>(xs0, xs1, xs2, xs3);

    // QKV projections
    qkv_mma<<<dim3(4, 16, 12), 256, GEMM_SMEM3>>>();

    // cross-stream attention (64-row q tiles, 3-stage KV pipeline)
    attn_h<<<dim3(8, 8, 16), 128, ATTN_SMEM3>>>(inter);

    // T1 = MH @ Wo + bo + x
    R4 rx; rx.p[0] = xs0; rx.p[1] = xs1; rx.p[2] = xs2; rx.p[3] = xs3;
    gemm_bias_resid<<<dim3(4, 16, 4), 256, GEMM_SMEM3>>>(mh, wo, bo, rx, t1, MROWS, EMB, EMB);

    // R1 = LN1(T1)  (fp32 + fp16 copies)
    ln_kernel<<<8192, 128>>>(t1, ln1g, ln1b, r1, r1h);

    // HB = gelu(R1h @ W1 + bf1)
    gemm_bias_gelu<<<dim3(16, 16, 4), 256, GEMM_SMEM3>>>(r1h, w1, bf1, hb, MROWS, 4 * EMB, EMB);

    // T2 = HB @ W2 + bf2 + R1
    R4 rr; for (int s = 0; s < 4; ++s) rr.p[s] = r1 + (size_t)s * MROWS * EMB;
    gemm_bias_resid<<<dim3(4, 16, 4), 256, GEMM_SMEM3>>>(hb, w2, bf2, rr, t2, MROWS, EMB, 2048);

    // out = LN2(T2)
    ln_kernel<<<8192, 128>>>(t2, ln2g, ln2b, (float*)d_out, nullptr);
}